// round 14
// baseline (speedup 1.0000x reference)
#include <cuda_runtime.h>
#include <cuda_bf16.h>
#include <math.h>
#include <stdint.h>

#define L_TOT 8500
#define DD 256
#define NH 8
#define NL 4
#define NP 4
#define DH 32
#define DFF 1024

// ---------------- fp32 scratch ----------------
__device__ float g_off[L_TOT * DD];
__device__ float g_attn[L_TOT * 128];
__device__ float g_x1[L_TOT * DD];
__device__ float g_tmp[L_TOT * DD];
// ---------------- bf16 scratch ----------------
__device__ __nv_bfloat16 g_qbf[L_TOT * DD];
__device__ __nv_bfloat16 g_srcbf[L_TOT * DD];
__device__ __nv_bfloat16 g_valbf[L_TOT * DD];
__device__ __nv_bfloat16 g_aobf[L_TOT * DD];
__device__ __nv_bfloat16 g_x1bf[L_TOT * DD];
__device__ __nv_bfloat16 g_hbf[L_TOT * DFF];
// weights bf16: Wo@0 Wa@65536 Wv@98304 Wout@163840 W1@229376 W2@491520
#define WOFF_O 0
#define WOFF_A 65536
#define WOFF_V 98304
#define WOFF_OUT 163840
#define WOFF_1 229376
#define WOFF_2 491520
#define WTOTAL 753664
__device__ __nv_bfloat16 g_wbf[WTOTAL];

// ---------------- helpers ----------------
__device__ __forceinline__ uint32_t smem_u32(const void* p) {
    uint32_t a;
    asm("{ .reg .u64 t; cvta.to.shared.u64 t, %1; cvt.u32.u64 %0, t; }" : "=r"(a) : "l"(p));
    return a;
}
__device__ __forceinline__ void cp_async16(uint32_t sa, const void* ga) {
    asm volatile("cp.async.cg.shared.global [%0], [%1], 16;" :: "r"(sa), "l"(ga));
}
__device__ __forceinline__ void cp_commit() {
    asm volatile("cp.async.commit_group;" ::: "memory");
}
template <int N_>
__device__ __forceinline__ void cp_wait() {
    asm volatile("cp.async.wait_group %0;" :: "n"(N_) : "memory");
}
__device__ __forceinline__ void grid_dep_sync() {
    asm volatile("griddepcontrol.wait;" ::: "memory");
}
__device__ __forceinline__ void mma_bf16(float* c, const uint32_t* a, const uint32_t* b) {
    asm volatile(
        "mma.sync.aligned.m16n8k16.row.col.f32.bf16.bf16.f32 "
        "{%0,%1,%2,%3}, {%4,%5,%6,%7}, {%8,%9}, {%0,%1,%2,%3};"
        : "+f"(c[0]), "+f"(c[1]), "+f"(c[2]), "+f"(c[3])
        : "r"(a[0]), "r"(a[1]), "r"(a[2]), "r"(a[3]), "r"(b[0]), "r"(b[1]));
}
#define LDSM_X4(r0, r1, r2, r3, addr) \
    asm volatile("ldmatrix.sync.aligned.m8n8.x4.shared.b16 {%0,%1,%2,%3}, [%4];" \
        : "=r"(r0), "=r"(r1), "=r"(r2), "=r"(r3) : "r"(addr))
#define LDSM_X4_T(r0, r1, r2, r3, addr) \
    asm volatile("ldmatrix.sync.aligned.m8n8.x4.trans.shared.b16 {%0,%1,%2,%3}, [%4];" \
        : "=r"(r0), "=r"(r1), "=r"(r2), "=r"(r3) : "r"(addr))

// ---------------- bf16 tensor-core GEMM ----------------
// block tile 64(M) x 64(N), BK=32, 8 slots / 7 in-flight stages, 128 threads
// = 4 warps (2x2), warp tile 32x32, single __syncthreads per K-iteration.
// A tile: 64 rows x 64B, 16B chunks XOR-swizzled (chunk ^ ((row>>1)&3)) ->
// conflict-free ldmatrix AND stores, no padding.  B tile: [32 k][72 bf16].
#define A_TILE_B 4096    // 64*64
#define B_TILE_B 4608    // 32*144
#define STAGES 8
#define GEMM_SMEM_BYTES (STAGES * (A_TILE_B + B_TILE_B))   // 69632

__device__ __forceinline__ void gemm_body(
    char* sm, const __nv_bfloat16* __restrict__ A, const __nv_bfloat16* __restrict__ W,
    const float* __restrict__ bias, float* __restrict__ C32, __nv_bfloat16* __restrict__ C16,
    int M, int N, int K, int relu, int blockRow, int blockCol, int lda)
{
    const uint32_t smem_base = smem_u32(sm);
    const uint32_t b_area = smem_base + STAGES * A_TILE_B;

    const int tid = threadIdx.x;
    const int wid = tid >> 5;
    const int lane = tid & 31;
    const int warp_m = wid >> 1;      // 0..1
    const int warp_n = wid & 1;       // 0..1
    const int tr = lane >> 2;
    const int tc = lane & 3;

    float acc[2][4][4];
    #pragma unroll
    for (int i = 0; i < 2; i++)
        #pragma unroll
        for (int j = 0; j < 4; j++)
            #pragma unroll
            for (int r = 0; r < 4; r++) acc[i][j][r] = 0.f;

    const int NC = K >> 5;

    auto issue_stage = [&](int s, int k0) {
        const uint32_t a_base = smem_base + (uint32_t)(s * A_TILE_B);
        const uint32_t b_base = b_area + (uint32_t)(s * B_TILE_B);
        // A: 256 chunks of 16B: chunk c -> row c>>2, kc c&3, XOR swizzle
        #pragma unroll
        for (int it = 0; it < 2; ++it) {
            const int c = tid + it * 128;
            const int row = c >> 2;
            const int kc = c & 3;
            int gr = blockRow + row;
            gr = gr < M - 1 ? gr : M - 1;
            const int pc = kc ^ ((row >> 1) & 3);
            cp_async16(a_base + (uint32_t)(row * 64 + pc * 16),
                       A + (size_t)gr * lda + k0 + kc * 8);
        }
        // B: 256 chunks: chunk c -> krow c>>3 (0..31), nc c&7
        #pragma unroll
        for (int it = 0; it < 2; ++it) {
            const int c = tid + it * 128;
            const int krow = c >> 3;
            const int nc = c & 7;
            cp_async16(b_base + (uint32_t)(krow * 144 + nc * 16),
                       W + (size_t)(k0 + krow) * N + blockCol + nc * 8);
        }
        cp_commit();
    };

    // PDL: wait for producer grid before reading its outputs
    grid_dep_sync();

    // prefetch 7 groups (empty commits when NC < 7 keep accounting exact)
    #pragma unroll
    for (int s = 0; s < 7; ++s) {
        if (s < NC) issue_stage(s, s << 5);
        else cp_commit();
    }

    const int amr = warp_m * 32;
    const int bnr = warp_n * 32;
    const int row_sel = lane & 15;
    const int k_sel = (lane >> 4) << 3;

    for (int i = 0; i < NC; ++i) {
        const int s = i & 7;
        cp_wait<6>();
        __syncthreads();
        if (i + 7 < NC) issue_stage((i + 7) & 7, (i + 7) << 5);
        else cp_commit();   // keep group count exact for cp_wait<6>

        const uint32_t a_base = smem_base + (uint32_t)(s * A_TILE_B);
        const uint32_t b_base = b_area + (uint32_t)(s * B_TILE_B);

        #pragma unroll
        for (int kb = 0; kb < 32; kb += 16) {
            uint32_t af[2][4];
            #pragma unroll
            for (int im = 0; im < 2; ++im) {
                const int row = amr + im * 16 + row_sel;
                const int chunk = (kb + k_sel) >> 3;
                const int pc = chunk ^ ((row >> 1) & 3);
                const uint32_t addr = a_base + (uint32_t)(row * 64 + pc * 16);
                LDSM_X4(af[im][0], af[im][1], af[im][2], af[im][3], addr);
            }
            uint32_t bfr[2][4];
            #pragma unroll
            for (int in2 = 0; in2 < 2; ++in2) {
                const uint32_t addr = b_base +
                    (uint32_t)(((kb + row_sel) * 72 + bnr + in2 * 16 + k_sel) * 2);
                LDSM_X4_T(bfr[in2][0], bfr[in2][1], bfr[in2][2], bfr[in2][3], addr);
            }
            #pragma unroll
            for (int im = 0; im < 2; ++im)
                #pragma unroll
                for (int in_ = 0; in_ < 4; ++in_)
                    mma_bf16(acc[im][in_], af[im], &bfr[in_ >> 1][(in_ & 1) * 2]);
        }
    }

    #pragma unroll
    for (int im = 0; im < 2; ++im) {
        const int row0 = blockRow + warp_m * 32 + im * 16 + tr;
        #pragma unroll
        for (int in_ = 0; in_ < 4; ++in_) {
            const int col = blockCol + warp_n * 32 + in_ * 8 + 2 * tc;
            const float bx = bias[col], by = bias[col + 1];
            float2 v0 = make_float2(acc[im][in_][0] + bx, acc[im][in_][1] + by);
            float2 v1 = make_float2(acc[im][in_][2] + bx, acc[im][in_][3] + by);
            if (relu) {
                v0.x = fmaxf(v0.x, 0.f); v0.y = fmaxf(v0.y, 0.f);
                v1.x = fmaxf(v1.x, 0.f); v1.y = fmaxf(v1.y, 0.f);
            }
            if (C32) {
                if (row0 < M)
                    *reinterpret_cast<float2*>(C32 + (size_t)row0 * N + col) = v0;
                if (row0 + 8 < M)
                    *reinterpret_cast<float2*>(C32 + (size_t)(row0 + 8) * N + col) = v1;
            }
            if (C16) {
                if (row0 < M) {
                    __nv_bfloat162 h0(__float2bfloat16_rn(v0.x), __float2bfloat16_rn(v0.y));
                    *reinterpret_cast<__nv_bfloat162*>(C16 + (size_t)row0 * N + col) = h0;
                }
                if (row0 + 8 < M) {
                    __nv_bfloat162 h1(__float2bfloat16_rn(v1.x), __float2bfloat16_rn(v1.y));
                    *reinterpret_cast<__nv_bfloat162*>(C16 + (size_t)(row0 + 8) * N + col) = h1;
                }
            }
        }
    }
}

__global__ void __launch_bounds__(128) gemm_std_kernel(
    const __nv_bfloat16* A, const __nv_bfloat16* W, const float* bias,
    float* C32, __nv_bfloat16* C16, int M, int N, int K, int relu, int lda)
{
    extern __shared__ char sm[];
    gemm_body(sm, A, W, bias, C32, C16, M, N, K, relu,
              blockIdx.y * 64, blockIdx.x * 64, lda);
}

// merged projections: gx 0-3 -> Wo -> off(f32); 4-5 -> Wa -> attn(f32);
// 6-9 -> Wv -> value(bf16)
__global__ void __launch_bounds__(128) gemm_proj_kernel(
    const __nv_bfloat16* qbf, const __nv_bfloat16* srcbf, const __nv_bfloat16* wbf,
    const float* bo, const float* ba, const float* bv,
    float* off, float* attn, __nv_bfloat16* valbf, int M)
{
    extern __shared__ char sm[];
    const int gx = blockIdx.x;
    const int br = blockIdx.y * 64;
    if (gx < 4)
        gemm_body(sm, qbf, wbf + WOFF_O, bo, off, nullptr, M, 256, 256, 0, br, gx * 64, 256);
    else if (gx < 6)
        gemm_body(sm, qbf, wbf + WOFF_A, ba, attn, nullptr, M, 128, 256, 0, br, (gx - 4) * 64, 256);
    else
        gemm_body(sm, srcbf, wbf + WOFF_V, bv, nullptr, valbf, M, 256, 256, 0, br, (gx - 6) * 64, 256);
}

// ---------------- fused prep (q/src -> bf16) + weight conversion ------------
#define NPREP (L_TOT * DD / 4)
#define NCONV (WTOTAL / 4)
__global__ void prep_conv_kernel(
    const float* __restrict__ src, const float* __restrict__ pos,
    __nv_bfloat16* __restrict__ qbf, __nv_bfloat16* __restrict__ srcbf,
    const float* w0, const float* w1, const float* w2,
    const float* w3, const float* w4, const float* w5,
    __nv_bfloat16* __restrict__ wdst)
{
    grid_dep_sync();
    int i = blockIdx.x * blockDim.x + threadIdx.x;
    if (i < NPREP) {
        float4 s = reinterpret_cast<const float4*>(src)[i];
        float4 p = reinterpret_cast<const float4*>(pos)[i];
        __nv_bfloat162 q0(__float2bfloat16_rn(s.x + p.x), __float2bfloat16_rn(s.y + p.y));
        __nv_bfloat162 q1(__float2bfloat16_rn(s.z + p.z), __float2bfloat16_rn(s.w + p.w));
        __nv_bfloat162 s0(__float2bfloat16_rn(s.x), __float2bfloat16_rn(s.y));
        __nv_bfloat162 s1(__float2bfloat16_rn(s.z), __float2bfloat16_rn(s.w));
        reinterpret_cast<__nv_bfloat162*>(qbf)[i * 2] = q0;
        reinterpret_cast<__nv_bfloat162*>(qbf)[i * 2 + 1] = q1;
        reinterpret_cast<__nv_bfloat162*>(srcbf)[i * 2] = s0;
        reinterpret_cast<__nv_bfloat162*>(srcbf)[i * 2 + 1] = s1;
        return;
    }
    int i4 = i - NPREP;
    if (i4 >= NCONV) return;
    int idx = i4 * 4;
    const float* srcw;
    int off;
    if (idx < WOFF_A)        { srcw = w0; off = 0; }
    else if (idx < WOFF_V)   { srcw = w1; off = WOFF_A; }
    else if (idx < WOFF_OUT) { srcw = w2; off = WOFF_V; }
    else if (idx < WOFF_1)   { srcw = w3; off = WOFF_OUT; }
    else if (idx < WOFF_2)   { srcw = w4; off = WOFF_1; }
    else                     { srcw = w5; off = WOFF_2; }
    float4 v = *reinterpret_cast<const float4*>(srcw + (idx - off));
    __nv_bfloat162 h0(__float2bfloat16_rn(v.x), __float2bfloat16_rn(v.y));
    __nv_bfloat162 h1(__float2bfloat16_rn(v.z), __float2bfloat16_rn(v.w));
    reinterpret_cast<__nv_bfloat162*>(wdst)[i4 * 2] = h0;
    reinterpret_cast<__nv_bfloat162*>(wdst)[i4 * 2 + 1] = h1;
}

// ---------------- msda v3: 1 warp/query, 4 lanes/head, bf16 value ----------
__global__ void __launch_bounds__(256) msda_kernel(
    const __nv_bfloat16* __restrict__ value,
    const float* __restrict__ off,
    const float* __restrict__ logits,
    const float* __restrict__ refpts,
    __nv_bfloat16* __restrict__ out)
{
    grid_dep_sync();
    const int lane = threadIdx.x & 31;
    const int l = blockIdx.x * 8 + (threadIdx.x >> 5);
    if (l >= L_TOT) return;
    const int h = lane >> 2;
    const int ln = lane & 3;

    const float4 lg = *reinterpret_cast<const float4*>(
        logits + (size_t)l * 128 + h * 16 + ln * 4);
    float m = fmaxf(fmaxf(lg.x, lg.y), fmaxf(lg.z, lg.w));
    #pragma unroll
    for (int o = 2; o > 0; o >>= 1) m = fmaxf(m, __shfl_xor_sync(0xffffffffu, m, o, 4));
    float4 e;
    e.x = __expf(lg.x - m); e.y = __expf(lg.y - m);
    e.z = __expf(lg.z - m); e.w = __expf(lg.w - m);
    float s = e.x + e.y + e.z + e.w;
    #pragma unroll
    for (int o = 2; o > 0; o >>= 1) s += __shfl_xor_sync(0xffffffffu, s, o, 4);
    const float inv = 1.f / s;
    const float4 w4 = make_float4(e.x * inv, e.y * inv, e.z * inv, e.w * inv);

    const float4 of0 = *reinterpret_cast<const float4*>(
        off + (size_t)l * DD + h * 32 + ln * 8);
    const float4 of1 = *reinterpret_cast<const float4*>(
        off + (size_t)l * DD + h * 32 + ln * 8 + 4);

    const __nv_bfloat16* vbase = value + h * DH + ln * 8;
    float acc[8] = {};

    const int Ws4[4] = {80, 40, 20, 10};
    const int starts[4] = {0, 6400, 8000, 8400};

    #pragma unroll
    for (int lvl = 0; lvl < NL; ++lvl) {
        const int Wl = Ws4[lvl], Hl = Ws4[lvl], st = starts[lvl];
        const float rx = refpts[(size_t)l * 8 + lvl * 2];
        const float ry = refpts[(size_t)l * 8 + lvl * 2 + 1];
        #pragma unroll
        for (int p = 0; p < NP; ++p) {
            const int pi = lvl * 4 + p;
            const int srcl = pi >> 2;
            const int j = pi & 3;
            const float ox = (j == 0) ? of0.x : (j == 1) ? of0.z : (j == 2) ? of1.x : of1.z;
            const float oy = (j == 0) ? of0.y : (j == 1) ? of0.w : (j == 2) ? of1.y : of1.w;
            const float ws = (j == 0) ? w4.x : (j == 1) ? w4.y : (j == 2) ? w4.z : w4.w;
            const float offx = __shfl_sync(0xffffffffu, ox, srcl, 4);
            const float offy = __shfl_sync(0xffffffffu, oy, srcl, 4);
            const float aw   = __shfl_sync(0xffffffffu, ws, srcl, 4);

            const float x = rx * Wl + offx - 0.5f;
            const float y = ry * Hl + offy - 0.5f;
            const int x0 = (int)floorf(x);
            const int y0 = (int)floorf(y);
            const float fx = x - x0;
            const float fy = y - y0;
            float samp[8] = {};
            #pragma unroll
            for (int dy = 0; dy < 2; ++dy) {
                #pragma unroll
                for (int dx = 0; dx < 2; ++dx) {
                    const int xi = x0 + dx;
                    const int yi = y0 + dy;
                    if (xi >= 0 && xi < Wl && yi >= 0 && yi < Hl) {
                        const float w = (dx ? fx : 1.f - fx) * (dy ? fy : 1.f - fy);
                        const uint4 raw = *reinterpret_cast<const uint4*>(
                            vbase + (size_t)(st + yi * Wl + xi) * DD);
                        const uint32_t rr[4] = {raw.x, raw.y, raw.z, raw.w};
                        #pragma unroll
                        for (int c = 0; c < 4; ++c) {
                            const float2 f = __bfloat1622float2(
                                *reinterpret_cast<const __nv_bfloat162*>(&rr[c]));
                            samp[c * 2 + 0] = fmaf(w, f.x, samp[c * 2 + 0]);
                            samp[c * 2 + 1] = fmaf(w, f.y, samp[c * 2 + 1]);
                        }
                    }
                }
            }
            #pragma unroll
            for (int c = 0; c < 8; ++c) acc[c] = fmaf(aw, samp[c], acc[c]);
        }
    }

    uint32_t packed[4];
    #pragma unroll
    for (int c = 0; c < 4; ++c) {
        __nv_bfloat162 pb(__float2bfloat16_rn(acc[c * 2]), __float2bfloat16_rn(acc[c * 2 + 1]));
        packed[c] = *reinterpret_cast<uint32_t*>(&pb);
    }
    *reinterpret_cast<uint4*>(out + (size_t)l * DD + h * DH + ln * 8) =
        make_uint4(packed[0], packed[1], packed[2], packed[3]);
}

// ---------------- fused residual add + LayerNorm ----------------
__global__ void add_ln_kernel(const float* __restrict__ a, const float* __restrict__ b,
                              const float* __restrict__ g, const float* __restrict__ be,
                              float* __restrict__ out, __nv_bfloat16* __restrict__ out_bf) {
    grid_dep_sync();
    const int row = blockIdx.x;
    const int t = threadIdx.x;
    const float v = a[(size_t)row * DD + t] + b[(size_t)row * DD + t];

    float s = v, s2 = v * v;
    __shared__ float sh[8], sh2[8];
    #pragma unroll
    for (int o = 16; o > 0; o >>= 1) {
        s  += __shfl_down_sync(0xffffffffu, s, o);
        s2 += __shfl_down_sync(0xffffffffu, s2, o);
    }
    const int w = t >> 5, lane = t & 31;
    if (lane == 0) { sh[w] = s; sh2[w] = s2; }
    __syncthreads();
    if (w == 0) {
        s  = (lane < 8) ? sh[lane]  : 0.f;
        s2 = (lane < 8) ? sh2[lane] : 0.f;
        #pragma unroll
        for (int o = 4; o > 0; o >>= 1) {
            s  += __shfl_down_sync(0xffffffffu, s, o);
            s2 += __shfl_down_sync(0xffffffffu, s2, o);
        }
        if (lane == 0) { sh[0] = s; sh2[0] = s2; }
    }
    __syncthreads();
    const float mean = sh[0] * (1.f / DD);
    const float var  = sh2[0] * (1.f / DD) - mean * mean;
    const float inv  = rsqrtf(var + 1e-5f);
    const float r = (v - mean) * inv * g[t] + be[t];
    out[(size_t)row * DD + t] = r;
    if (out_bf) out_bf[(size_t)row * DD + t] = __float2bfloat16_rn(r);
}

// ---------------- PDL launcher ----------------
static inline void launch_pdl(const void* func, dim3 grid, dim3 block,
                              size_t smem, void** args) {
    cudaLaunchConfig_t cfg = {};
    cfg.gridDim = grid;
    cfg.blockDim = block;
    cfg.dynamicSmemBytes = smem;
    cfg.stream = 0;
    cudaLaunchAttribute attr;
    attr.id = cudaLaunchAttributeProgrammaticStreamSerialization;
    attr.val.programmaticStreamSerializationAllowed = 1;
    cfg.attrs = &attr;
    cfg.numAttrs = 1;
    cudaLaunchKernelExC(&cfg, func, args);
}

// ---------------- launch ----------------
extern "C" void kernel_launch(void* const* d_in, const int* in_sizes, int n_in,
                              void* d_out, int out_size) {
    const float* src  = (const float*)d_in[0];
    const float* pos  = (const float*)d_in[1];
    const float* refp = (const float*)d_in[2];
    const float* Wo   = (const float*)d_in[6];
    const float* bo   = (const float*)d_in[7];
    const float* Wa   = (const float*)d_in[8];
    const float* ba   = (const float*)d_in[9];
    const float* Wv   = (const float*)d_in[10];
    const float* bv   = (const float*)d_in[11];
    const float* Wout = (const float*)d_in[12];
    const float* bout = (const float*)d_in[13];
    const float* W1   = (const float*)d_in[14];
    const float* b1   = (const float*)d_in[15];
    const float* W2   = (const float*)d_in[16];
    const float* b2   = (const float*)d_in[17];
    const float* g1   = (const float*)d_in[18];
    const float* be1  = (const float*)d_in[19];
    const float* g2   = (const float*)d_in[20];
    const float* be2  = (const float*)d_in[21];
    float* out = (float*)d_out;

    float *off, *attn, *x1, *tmp;
    __nv_bfloat16 *qbf, *srcbf, *valbf, *aobf, *x1bf, *hbf, *wbf;
    cudaGetSymbolAddress((void**)&off,   g_off);
    cudaGetSymbolAddress((void**)&attn,  g_attn);
    cudaGetSymbolAddress((void**)&x1,    g_x1);
    cudaGetSymbolAddress((void**)&tmp,   g_tmp);
    cudaGetSymbolAddress((void**)&qbf,   g_qbf);
    cudaGetSymbolAddress((void**)&srcbf, g_srcbf);
    cudaGetSymbolAddress((void**)&valbf, g_valbf);
    cudaGetSymbolAddress((void**)&aobf,  g_aobf);
    cudaGetSymbolAddress((void**)&x1bf,  g_x1bf);
    cudaGetSymbolAddress((void**)&hbf,   g_hbf);
    cudaGetSymbolAddress((void**)&wbf,   g_wbf);

    static int smem_set = 0;
    if (!smem_set) {
        cudaFuncSetAttribute(gemm_std_kernel,
                             cudaFuncAttributeMaxDynamicSharedMemorySize, GEMM_SMEM_BYTES);
        cudaFuncSetAttribute(gemm_proj_kernel,
                             cudaFuncAttributeMaxDynamicSharedMemorySize, GEMM_SMEM_BYTES);
        smem_set = 1;
    }

    int M = L_TOT;
    const int MT = (M + 63) / 64;    // 133

    // 0) prep + weight conversion
    {
        void* args[] = {(void*)&src, (void*)&pos, (void*)&qbf, (void*)&srcbf,
                        (void*)&Wo, (void*)&Wa, (void*)&Wv, (void*)&Wout,
                        (void*)&W1, (void*)&W2, (void*)&wbf};
        launch_pdl((const void*)prep_conv_kernel,
                   dim3((NPREP + NCONV + 255) / 256), dim3(256), 0, args);
    }

    // 1) merged projections: off(f32), attn(f32), value(bf16)
    {
        void* args[] = {(void*)&qbf, (void*)&srcbf, (void*)&wbf,
                        (void*)&bo, (void*)&ba, (void*)&bv,
                        (void*)&off, (void*)&attn, (void*)&valbf, (void*)&M};
        launch_pdl((const void*)gemm_proj_kernel,
                   dim3(10, MT), dim3(128), GEMM_SMEM_BYTES, args);
    }

    // 2) deformable attention (fused softmax) -> bf16
    {
        void* args[] = {(void*)&valbf, (void*)&off, (void*)&attn,
                        (void*)&refp, (void*)&aobf};
        launch_pdl((const void*)msda_kernel,
                   dim3((M + 7) / 8), dim3(256), 0, args);
    }

    // 3) src2 = attnout @ Wout + bout
    {
        int N = 256, K = 256, relu = 0, lda = 256;
        const __nv_bfloat16* Aarg = aobf;
        const __nv_bfloat16* Warg = wbf + WOFF_OUT;
        float* C32 = tmp;
        __nv_bfloat16* C16 = nullptr;
        void* args[] = {(void*)&Aarg, (void*)&Warg, (void*)&bout,
                        (void*)&C32, (void*)&C16, (void*)&M, (void*)&N,
                        (void*)&K, (void*)&relu, (void*)&lda};
        launch_pdl((const void*)gemm_std_kernel,
                   dim3(4, MT), dim3(128), GEMM_SMEM_BYTES, args);
    }

    // 4) x1 = LN(src + src2) (+ bf16 copy)
    {
        void* args[] = {(void*)&src, (void*)&tmp, (void*)&g1, (void*)&be1,
                        (void*)&x1, (void*)&x1bf};
        launch_pdl((const void*)add_ln_kernel, dim3(M), dim3(256), 0, args);
    }

    // 5) h = relu(x1 @ W1 + b1) -> bf16
    {
        int N = 1024, K = 256, relu = 1, lda = 256;
        const __nv_bfloat16* Aarg = x1bf;
        const __nv_bfloat16* Warg = wbf + WOFF_1;
        float* C32 = nullptr;
        __nv_bfloat16* C16 = hbf;
        void* args[] = {(void*)&Aarg, (void*)&Warg, (void*)&b1,
                        (void*)&C32, (void*)&C16, (void*)&M, (void*)&N,
                        (void*)&K, (void*)&relu, (void*)&lda};
        launch_pdl((const void*)gemm_std_kernel,
                   dim3(16, MT), dim3(128), GEMM_SMEM_BYTES, args);
    }

    // 6) tmp = h @ W2 + b2
    {
        int N = 256, K = 1024, relu = 0, lda = 1024;
        const __nv_bfloat16* Aarg = hbf;
        const __nv_bfloat16* Warg = wbf + WOFF_2;
        float* C32 = tmp;
        __nv_bfloat16* C16 = nullptr;
        void* args[] = {(void*)&Aarg, (void*)&Warg, (void*)&b2,
                        (void*)&C32, (void*)&C16, (void*)&M, (void*)&N,
                        (void*)&K, (void*)&relu, (void*)&lda};
        launch_pdl((const void*)gemm_std_kernel,
                   dim3(4, MT), dim3(128), GEMM_SMEM_BYTES, args);
    }

    // 7) out = LN(x1 + tmp)
    {
        __nv_bfloat16* nobf = nullptr;
        void* args[] = {(void*)&x1, (void*)&tmp, (void*)&g2, (void*)&be2,
                        (void*)&out, (void*)&nobf};
        launch_pdl((const void*)add_ln_kernel, dim3(M), dim3(256), 0, args);
    }
}

// round 15
// speedup vs baseline: 1.1176x; 1.1176x over previous
#include <cuda_runtime.h>
#include <cuda_bf16.h>
#include <math.h>
#include <stdint.h>

#define L_TOT 8500
#define DD 256
#define NH 8
#define NL 4
#define NP 4
#define DH 32
#define DFF 1024

// ---------------- fp32 scratch ----------------
__device__ float g_off[L_TOT * DD];
__device__ float g_attn[L_TOT * 128];
__device__ float g_x1[L_TOT * DD];
__device__ float g_tmp[L_TOT * DD];
// ---------------- bf16 scratch ----------------
__device__ __nv_bfloat16 g_qbf[L_TOT * DD];
__device__ __nv_bfloat16 g_srcbf[L_TOT * DD];
__device__ __nv_bfloat16 g_valbf[L_TOT * DD];
__device__ __nv_bfloat16 g_aobf[L_TOT * DD];
__device__ __nv_bfloat16 g_x1bf[L_TOT * DD];
__device__ __nv_bfloat16 g_hbf[L_TOT * DFF];
// weights bf16: Wo@0 Wa@65536 Wv@98304 Wout@163840 W1@229376 W2@491520
#define WOFF_O 0
#define WOFF_A 65536
#define WOFF_V 98304
#define WOFF_OUT 163840
#define WOFF_1 229376
#define WOFF_2 491520
#define WTOTAL 753664
__device__ __nv_bfloat16 g_wbf[WTOTAL];

// ---------------- helpers ----------------
__device__ __forceinline__ uint32_t smem_u32(const void* p) {
    uint32_t a;
    asm("{ .reg .u64 t; cvta.to.shared.u64 t, %1; cvt.u32.u64 %0, t; }" : "=r"(a) : "l"(p));
    return a;
}
__device__ __forceinline__ void cp_async16(uint32_t sa, const void* ga) {
    asm volatile("cp.async.cg.shared.global [%0], [%1], 16;" :: "r"(sa), "l"(ga));
}
__device__ __forceinline__ void cp_commit() {
    asm volatile("cp.async.commit_group;" ::: "memory");
}
template <int N_>
__device__ __forceinline__ void cp_wait() {
    asm volatile("cp.async.wait_group %0;" :: "n"(N_) : "memory");
}
__device__ __forceinline__ void grid_dep_sync() {
    asm volatile("griddepcontrol.wait;" ::: "memory");
}
__device__ __forceinline__ void mma_bf16(float* c, const uint32_t* a, const uint32_t* b) {
    asm volatile(
        "mma.sync.aligned.m16n8k16.row.col.f32.bf16.bf16.f32 "
        "{%0,%1,%2,%3}, {%4,%5,%6,%7}, {%8,%9}, {%0,%1,%2,%3};"
        : "+f"(c[0]), "+f"(c[1]), "+f"(c[2]), "+f"(c[3])
        : "r"(a[0]), "r"(a[1]), "r"(a[2]), "r"(a[3]), "r"(b[0]), "r"(b[1]));
}
#define LDSM_X4(r0, r1, r2, r3, addr) \
    asm volatile("ldmatrix.sync.aligned.m8n8.x4.shared.b16 {%0,%1,%2,%3}, [%4];" \
        : "=r"(r0), "=r"(r1), "=r"(r2), "=r"(r3) : "r"(addr))
#define LDSM_X4_T(r0, r1, r2, r3, addr) \
    asm volatile("ldmatrix.sync.aligned.m8n8.x4.trans.shared.b16 {%0,%1,%2,%3}, [%4];" \
        : "=r"(r0), "=r"(r1), "=r"(r2), "=r"(r3) : "r"(addr))

// ---------------- bf16 tensor-core GEMM ----------------
// R13 pipeline (4 slots / 3 in flight, wait<2>, single sync) + XOR-swizzled
// unpadded A tile (64B rows, conflict-free LDSM & stores).
#define A_TILE_B 4096    // 64 rows * 64 B
#define B_TILE_B 4608    // 32 * 144 B
#define STAGES 4
#define GEMM_SMEM_BYTES (STAGES * (A_TILE_B + B_TILE_B))   // 34816

__device__ __forceinline__ void gemm_body(
    char* sm, const __nv_bfloat16* __restrict__ A, const __nv_bfloat16* __restrict__ W,
    const float* __restrict__ bias, float* __restrict__ C32, __nv_bfloat16* __restrict__ C16,
    int M, int N, int K, int relu, int blockRow, int blockCol, int lda)
{
    const uint32_t smem_base = smem_u32(sm);
    const uint32_t b_area = smem_base + STAGES * A_TILE_B;

    const int tid = threadIdx.x;
    const int wid = tid >> 5;
    const int lane = tid & 31;
    const int warp_m = wid >> 1;      // 0..1
    const int warp_n = wid & 1;       // 0..1
    const int tr = lane >> 2;
    const int tc = lane & 3;

    float acc[2][4][4];
    #pragma unroll
    for (int i = 0; i < 2; i++)
        #pragma unroll
        for (int j = 0; j < 4; j++)
            #pragma unroll
            for (int r = 0; r < 4; r++) acc[i][j][r] = 0.f;

    const int NC = K >> 5;

    auto issue_stage = [&](int s, int k0) {
        const uint32_t a_base = smem_base + (uint32_t)(s * A_TILE_B);
        const uint32_t b_base = b_area + (uint32_t)(s * B_TILE_B);
        // A: 256 chunks of 16B: chunk c -> row c>>2, kc c&3, XOR swizzle
        #pragma unroll
        for (int it = 0; it < 2; ++it) {
            const int c = tid + it * 128;
            const int row = c >> 2;
            const int kc = c & 3;
            int gr = blockRow + row;
            gr = gr < M - 1 ? gr : M - 1;
            const int pc = kc ^ ((row >> 1) & 3);
            cp_async16(a_base + (uint32_t)(row * 64 + pc * 16),
                       A + (size_t)gr * lda + k0 + kc * 8);
        }
        // B: 256 chunks: chunk c -> krow c>>3 (0..31), nc c&7
        #pragma unroll
        for (int it = 0; it < 2; ++it) {
            const int c = tid + it * 128;
            const int krow = c >> 3;
            const int nc = c & 7;
            cp_async16(b_base + (uint32_t)(krow * 144 + nc * 16),
                       W + (size_t)(k0 + krow) * N + blockCol + nc * 8);
        }
        cp_commit();
    };

    // PDL: wait for producer grid before reading its outputs
    grid_dep_sync();

    issue_stage(0, 0);
    issue_stage(1, 32);
    issue_stage(2, 64);

    const int amr = warp_m * 32;
    const int bnr = warp_n * 32;
    const int row_sel = lane & 15;
    const int k_sel = (lane >> 4) << 3;

    for (int i = 0; i < NC; ++i) {
        const int s = i & 3;
        cp_wait<2>();
        __syncthreads();
        if (i + 3 < NC) issue_stage((i + 3) & 3, (i + 3) << 5);
        else cp_commit();   // keep group count exact for cp_wait<2>

        const uint32_t a_base = smem_base + (uint32_t)(s * A_TILE_B);
        const uint32_t b_base = b_area + (uint32_t)(s * B_TILE_B);

        #pragma unroll
        for (int kb = 0; kb < 32; kb += 16) {
            uint32_t af[2][4];
            #pragma unroll
            for (int im = 0; im < 2; ++im) {
                const int row = amr + im * 16 + row_sel;
                const int chunk = (kb + k_sel) >> 3;
                const int pc = chunk ^ ((row >> 1) & 3);
                const uint32_t addr = a_base + (uint32_t)(row * 64 + pc * 16);
                LDSM_X4(af[im][0], af[im][1], af[im][2], af[im][3], addr);
            }
            uint32_t bfr[2][4];
            #pragma unroll
            for (int in2 = 0; in2 < 2; ++in2) {
                const uint32_t addr = b_base +
                    (uint32_t)(((kb + row_sel) * 72 + bnr + in2 * 16 + k_sel) * 2);
                LDSM_X4_T(bfr[in2][0], bfr[in2][1], bfr[in2][2], bfr[in2][3], addr);
            }
            #pragma unroll
            for (int im = 0; im < 2; ++im)
                #pragma unroll
                for (int in_ = 0; in_ < 4; ++in_)
                    mma_bf16(acc[im][in_], af[im], &bfr[in_ >> 1][(in_ & 1) * 2]);
        }
    }

    #pragma unroll
    for (int im = 0; im < 2; ++im) {
        const int row0 = blockRow + warp_m * 32 + im * 16 + tr;
        #pragma unroll
        for (int in_ = 0; in_ < 4; ++in_) {
            const int col = blockCol + warp_n * 32 + in_ * 8 + 2 * tc;
            const float bx = bias[col], by = bias[col + 1];
            float2 v0 = make_float2(acc[im][in_][0] + bx, acc[im][in_][1] + by);
            float2 v1 = make_float2(acc[im][in_][2] + bx, acc[im][in_][3] + by);
            if (relu) {
                v0.x = fmaxf(v0.x, 0.f); v0.y = fmaxf(v0.y, 0.f);
                v1.x = fmaxf(v1.x, 0.f); v1.y = fmaxf(v1.y, 0.f);
            }
            if (C32) {
                if (row0 < M)
                    *reinterpret_cast<float2*>(C32 + (size_t)row0 * N + col) = v0;
                if (row0 + 8 < M)
                    *reinterpret_cast<float2*>(C32 + (size_t)(row0 + 8) * N + col) = v1;
            }
            if (C16) {
                if (row0 < M) {
                    __nv_bfloat162 h0(__float2bfloat16_rn(v0.x), __float2bfloat16_rn(v0.y));
                    *reinterpret_cast<__nv_bfloat162*>(C16 + (size_t)row0 * N + col) = h0;
                }
                if (row0 + 8 < M) {
                    __nv_bfloat162 h1(__float2bfloat16_rn(v1.x), __float2bfloat16_rn(v1.y));
                    *reinterpret_cast<__nv_bfloat162*>(C16 + (size_t)(row0 + 8) * N + col) = h1;
                }
            }
        }
    }
}

__global__ void __launch_bounds__(128) gemm_std_kernel(
    const __nv_bfloat16* A, const __nv_bfloat16* W, const float* bias,
    float* C32, __nv_bfloat16* C16, int M, int N, int K, int relu, int lda)
{
    extern __shared__ char sm[];
    gemm_body(sm, A, W, bias, C32, C16, M, N, K, relu,
              blockIdx.y * 64, blockIdx.x * 64, lda);
}

// merged projections: gx 0-3 -> Wo -> off(f32); 4-5 -> Wa -> attn(f32);
// 6-9 -> Wv -> value(bf16)
__global__ void __launch_bounds__(128) gemm_proj_kernel(
    const __nv_bfloat16* qbf, const __nv_bfloat16* srcbf, const __nv_bfloat16* wbf,
    const float* bo, const float* ba, const float* bv,
    float* off, float* attn, __nv_bfloat16* valbf, int M)
{
    extern __shared__ char sm[];
    const int gx = blockIdx.x;
    const int br = blockIdx.y * 64;
    if (gx < 4)
        gemm_body(sm, qbf, wbf + WOFF_O, bo, off, nullptr, M, 256, 256, 0, br, gx * 64, 256);
    else if (gx < 6)
        gemm_body(sm, qbf, wbf + WOFF_A, ba, attn, nullptr, M, 128, 256, 0, br, (gx - 4) * 64, 256);
    else
        gemm_body(sm, srcbf, wbf + WOFF_V, bv, nullptr, valbf, M, 256, 256, 0, br, (gx - 6) * 64, 256);
}

// ---------------- fused prep (q/src -> bf16) + weight conversion ------------
#define NPREP (L_TOT * DD / 4)
#define NCONV (WTOTAL / 4)
__global__ void prep_conv_kernel(
    const float* __restrict__ src, const float* __restrict__ pos,
    __nv_bfloat16* __restrict__ qbf, __nv_bfloat16* __restrict__ srcbf,
    const float* w0, const float* w1, const float* w2,
    const float* w3, const float* w4, const float* w5,
    __nv_bfloat16* __restrict__ wdst)
{
    grid_dep_sync();
    int i = blockIdx.x * blockDim.x + threadIdx.x;
    if (i < NPREP) {
        float4 s = reinterpret_cast<const float4*>(src)[i];
        float4 p = reinterpret_cast<const float4*>(pos)[i];
        __nv_bfloat162 q0(__float2bfloat16_rn(s.x + p.x), __float2bfloat16_rn(s.y + p.y));
        __nv_bfloat162 q1(__float2bfloat16_rn(s.z + p.z), __float2bfloat16_rn(s.w + p.w));
        __nv_bfloat162 s0(__float2bfloat16_rn(s.x), __float2bfloat16_rn(s.y));
        __nv_bfloat162 s1(__float2bfloat16_rn(s.z), __float2bfloat16_rn(s.w));
        reinterpret_cast<__nv_bfloat162*>(qbf)[i * 2] = q0;
        reinterpret_cast<__nv_bfloat162*>(qbf)[i * 2 + 1] = q1;
        reinterpret_cast<__nv_bfloat162*>(srcbf)[i * 2] = s0;
        reinterpret_cast<__nv_bfloat162*>(srcbf)[i * 2 + 1] = s1;
        return;
    }
    int i4 = i - NPREP;
    if (i4 >= NCONV) return;
    int idx = i4 * 4;
    const float* srcw;
    int off;
    if (idx < WOFF_A)        { srcw = w0; off = 0; }
    else if (idx < WOFF_V)   { srcw = w1; off = WOFF_A; }
    else if (idx < WOFF_OUT) { srcw = w2; off = WOFF_V; }
    else if (idx < WOFF_1)   { srcw = w3; off = WOFF_OUT; }
    else if (idx < WOFF_2)   { srcw = w4; off = WOFF_1; }
    else                     { srcw = w5; off = WOFF_2; }
    float4 v = *reinterpret_cast<const float4*>(srcw + (idx - off));
    __nv_bfloat162 h0(__float2bfloat16_rn(v.x), __float2bfloat16_rn(v.y));
    __nv_bfloat162 h1(__float2bfloat16_rn(v.z), __float2bfloat16_rn(v.w));
    reinterpret_cast<__nv_bfloat162*>(wdst)[i4 * 2] = h0;
    reinterpret_cast<__nv_bfloat162*>(wdst)[i4 * 2 + 1] = h1;
}

// ---------------- msda v3: 1 warp/query, 4 lanes/head, bf16 value ----------
__global__ void __launch_bounds__(256) msda_kernel(
    const __nv_bfloat16* __restrict__ value,
    const float* __restrict__ off,
    const float* __restrict__ logits,
    const float* __restrict__ refpts,
    __nv_bfloat16* __restrict__ out)
{
    grid_dep_sync();
    const int lane = threadIdx.x & 31;
    const int l = blockIdx.x * 8 + (threadIdx.x >> 5);
    if (l >= L_TOT) return;
    const int h = lane >> 2;
    const int ln = lane & 3;

    const float4 lg = *reinterpret_cast<const float4*>(
        logits + (size_t)l * 128 + h * 16 + ln * 4);
    float m = fmaxf(fmaxf(lg.x, lg.y), fmaxf(lg.z, lg.w));
    #pragma unroll
    for (int o = 2; o > 0; o >>= 1) m = fmaxf(m, __shfl_xor_sync(0xffffffffu, m, o, 4));
    float4 e;
    e.x = __expf(lg.x - m); e.y = __expf(lg.y - m);
    e.z = __expf(lg.z - m); e.w = __expf(lg.w - m);
    float s = e.x + e.y + e.z + e.w;
    #pragma unroll
    for (int o = 2; o > 0; o >>= 1) s += __shfl_xor_sync(0xffffffffu, s, o, 4);
    const float inv = 1.f / s;
    const float4 w4 = make_float4(e.x * inv, e.y * inv, e.z * inv, e.w * inv);

    const float4 of0 = *reinterpret_cast<const float4*>(
        off + (size_t)l * DD + h * 32 + ln * 8);
    const float4 of1 = *reinterpret_cast<const float4*>(
        off + (size_t)l * DD + h * 32 + ln * 8 + 4);

    const __nv_bfloat16* vbase = value + h * DH + ln * 8;
    float acc[8] = {};

    const int Ws4[4] = {80, 40, 20, 10};
    const int starts[4] = {0, 6400, 8000, 8400};

    #pragma unroll
    for (int lvl = 0; lvl < NL; ++lvl) {
        const int Wl = Ws4[lvl], Hl = Ws4[lvl], st = starts[lvl];
        const float rx = refpts[(size_t)l * 8 + lvl * 2];
        const float ry = refpts[(size_t)l * 8 + lvl * 2 + 1];
        #pragma unroll
        for (int p = 0; p < NP; ++p) {
            const int pi = lvl * 4 + p;
            const int srcl = pi >> 2;
            const int j = pi & 3;
            const float ox = (j == 0) ? of0.x : (j == 1) ? of0.z : (j == 2) ? of1.x : of1.z;
            const float oy = (j == 0) ? of0.y : (j == 1) ? of0.w : (j == 2) ? of1.y : of1.w;
            const float ws = (j == 0) ? w4.x : (j == 1) ? w4.y : (j == 2) ? w4.z : w4.w;
            const float offx = __shfl_sync(0xffffffffu, ox, srcl, 4);
            const float offy = __shfl_sync(0xffffffffu, oy, srcl, 4);
            const float aw   = __shfl_sync(0xffffffffu, ws, srcl, 4);

            const float x = rx * Wl + offx - 0.5f;
            const float y = ry * Hl + offy - 0.5f;
            const int x0 = (int)floorf(x);
            const int y0 = (int)floorf(y);
            const float fx = x - x0;
            const float fy = y - y0;
            float samp[8] = {};
            #pragma unroll
            for (int dy = 0; dy < 2; ++dy) {
                #pragma unroll
                for (int dx = 0; dx < 2; ++dx) {
                    const int xi = x0 + dx;
                    const int yi = y0 + dy;
                    if (xi >= 0 && xi < Wl && yi >= 0 && yi < Hl) {
                        const float w = (dx ? fx : 1.f - fx) * (dy ? fy : 1.f - fy);
                        const uint4 raw = *reinterpret_cast<const uint4*>(
                            vbase + (size_t)(st + yi * Wl + xi) * DD);
                        const uint32_t rr[4] = {raw.x, raw.y, raw.z, raw.w};
                        #pragma unroll
                        for (int c = 0; c < 4; ++c) {
                            const float2 f = __bfloat1622float2(
                                *reinterpret_cast<const __nv_bfloat162*>(&rr[c]));
                            samp[c * 2 + 0] = fmaf(w, f.x, samp[c * 2 + 0]);
                            samp[c * 2 + 1] = fmaf(w, f.y, samp[c * 2 + 1]);
                        }
                    }
                }
            }
            #pragma unroll
            for (int c = 0; c < 8; ++c) acc[c] = fmaf(aw, samp[c], acc[c]);
        }
    }

    uint32_t packed[4];
    #pragma unroll
    for (int c = 0; c < 4; ++c) {
        __nv_bfloat162 pb(__float2bfloat16_rn(acc[c * 2]), __float2bfloat16_rn(acc[c * 2 + 1]));
        packed[c] = *reinterpret_cast<uint32_t*>(&pb);
    }
    *reinterpret_cast<uint4*>(out + (size_t)l * DD + h * DH + ln * 8) =
        make_uint4(packed[0], packed[1], packed[2], packed[3]);
}

// ---------------- fused residual add + LayerNorm ----------------
__global__ void add_ln_kernel(const float* __restrict__ a, const float* __restrict__ b,
                              const float* __restrict__ g, const float* __restrict__ be,
                              float* __restrict__ out, __nv_bfloat16* __restrict__ out_bf) {
    grid_dep_sync();
    const int row = blockIdx.x;
    const int t = threadIdx.x;
    const float v = a[(size_t)row * DD + t] + b[(size_t)row * DD + t];

    float s = v, s2 = v * v;
    __shared__ float sh[8], sh2[8];
    #pragma unroll
    for (int o = 16; o > 0; o >>= 1) {
        s  += __shfl_down_sync(0xffffffffu, s, o);
        s2 += __shfl_down_sync(0xffffffffu, s2, o);
    }
    const int w = t >> 5, lane = t & 31;
    if (lane == 0) { sh[w] = s; sh2[w] = s2; }
    __syncthreads();
    if (w == 0) {
        s  = (lane < 8) ? sh[lane]  : 0.f;
        s2 = (lane < 8) ? sh2[lane] : 0.f;
        #pragma unroll
        for (int o = 4; o > 0; o >>= 1) {
            s  += __shfl_down_sync(0xffffffffu, s, o);
            s2 += __shfl_down_sync(0xffffffffu, s2, o);
        }
        if (lane == 0) { sh[0] = s; sh2[0] = s2; }
    }
    __syncthreads();
    const float mean = sh[0] * (1.f / DD);
    const float var  = sh2[0] * (1.f / DD) - mean * mean;
    const float inv  = rsqrtf(var + 1e-5f);
    const float r = (v - mean) * inv * g[t] + be[t];
    out[(size_t)row * DD + t] = r;
    if (out_bf) out_bf[(size_t)row * DD + t] = __float2bfloat16_rn(r);
}

// ---------------- PDL launcher ----------------
static inline void launch_pdl(const void* func, dim3 grid, dim3 block,
                              size_t smem, void** args) {
    cudaLaunchConfig_t cfg = {};
    cfg.gridDim = grid;
    cfg.blockDim = block;
    cfg.dynamicSmemBytes = smem;
    cfg.stream = 0;
    cudaLaunchAttribute attr;
    attr.id = cudaLaunchAttributeProgrammaticStreamSerialization;
    attr.val.programmaticStreamSerializationAllowed = 1;
    cfg.attrs = &attr;
    cfg.numAttrs = 1;
    cudaLaunchKernelExC(&cfg, func, args);
}

// ---------------- launch ----------------
extern "C" void kernel_launch(void* const* d_in, const int* in_sizes, int n_in,
                              void* d_out, int out_size) {
    const float* src  = (const float*)d_in[0];
    const float* pos  = (const float*)d_in[1];
    const float* refp = (const float*)d_in[2];
    const float* Wo   = (const float*)d_in[6];
    const float* bo   = (const float*)d_in[7];
    const float* Wa   = (const float*)d_in[8];
    const float* ba   = (const float*)d_in[9];
    const float* Wv   = (const float*)d_in[10];
    const float* bv   = (const float*)d_in[11];
    const float* Wout = (const float*)d_in[12];
    const float* bout = (const float*)d_in[13];
    const float* W1   = (const float*)d_in[14];
    const float* b1   = (const float*)d_in[15];
    const float* W2   = (const float*)d_in[16];
    const float* b2   = (const float*)d_in[17];
    const float* g1   = (const float*)d_in[18];
    const float* be1  = (const float*)d_in[19];
    const float* g2   = (const float*)d_in[20];
    const float* be2  = (const float*)d_in[21];
    float* out = (float*)d_out;

    float *off, *attn, *x1, *tmp;
    __nv_bfloat16 *qbf, *srcbf, *valbf, *aobf, *x1bf, *hbf, *wbf;
    cudaGetSymbolAddress((void**)&off,   g_off);
    cudaGetSymbolAddress((void**)&attn,  g_attn);
    cudaGetSymbolAddress((void**)&x1,    g_x1);
    cudaGetSymbolAddress((void**)&tmp,   g_tmp);
    cudaGetSymbolAddress((void**)&qbf,   g_qbf);
    cudaGetSymbolAddress((void**)&srcbf, g_srcbf);
    cudaGetSymbolAddress((void**)&valbf, g_valbf);
    cudaGetSymbolAddress((void**)&aobf,  g_aobf);
    cudaGetSymbolAddress((void**)&x1bf,  g_x1bf);
    cudaGetSymbolAddress((void**)&hbf,   g_hbf);
    cudaGetSymbolAddress((void**)&wbf,   g_wbf);

    static int smem_set = 0;
    if (!smem_set) {
        cudaFuncSetAttribute(gemm_std_kernel,
                             cudaFuncAttributeMaxDynamicSharedMemorySize, GEMM_SMEM_BYTES);
        cudaFuncSetAttribute(gemm_proj_kernel,
                             cudaFuncAttributeMaxDynamicSharedMemorySize, GEMM_SMEM_BYTES);
        smem_set = 1;
    }

    int M = L_TOT;
    const int MT = (M + 63) / 64;    // 133

    // 0) prep + weight conversion
    {
        void* args[] = {(void*)&src, (void*)&pos, (void*)&qbf, (void*)&srcbf,
                        (void*)&Wo, (void*)&Wa, (void*)&Wv, (void*)&Wout,
                        (void*)&W1, (void*)&W2, (void*)&wbf};
        launch_pdl((const void*)prep_conv_kernel,
                   dim3((NPREP + NCONV + 255) / 256), dim3(256), 0, args);
    }

    // 1) merged projections: off(f32), attn(f32), value(bf16)
    {
        void* args[] = {(void*)&qbf, (void*)&srcbf, (void*)&wbf,
                        (void*)&bo, (void*)&ba, (void*)&bv,
                        (void*)&off, (void*)&attn, (void*)&valbf, (void*)&M};
        launch_pdl((const void*)gemm_proj_kernel,
                   dim3(10, MT), dim3(128), GEMM_SMEM_BYTES, args);
    }

    // 2) deformable attention (fused softmax) -> bf16
    {
        void* args[] = {(void*)&valbf, (void*)&off, (void*)&attn,
                        (void*)&refp, (void*)&aobf};
        launch_pdl((const void*)msda_kernel,
                   dim3((M + 7) / 8), dim3(256), 0, args);
    }

    // 3) src2 = attnout @ Wout + bout
    {
        int N = 256, K = 256, relu = 0, lda = 256;
        const __nv_bfloat16* Aarg = aobf;
        const __nv_bfloat16* Warg = wbf + WOFF_OUT;
        float* C32 = tmp;
        __nv_bfloat16* C16 = nullptr;
        void* args[] = {(void*)&Aarg, (void*)&Warg, (void*)&bout,
                        (void*)&C32, (void*)&C16, (void*)&M, (void*)&N,
                        (void*)&K, (void*)&relu, (void*)&lda};
        launch_pdl((const void*)gemm_std_kernel,
                   dim3(4, MT), dim3(128), GEMM_SMEM_BYTES, args);
    }

    // 4) x1 = LN(src + src2) (+ bf16 copy)
    {
        void* args[] = {(void*)&src, (void*)&tmp, (void*)&g1, (void*)&be1,
                        (void*)&x1, (void*)&x1bf};
        launch_pdl((const void*)add_ln_kernel, dim3(M), dim3(256), 0, args);
    }

    // 5) h = relu(x1 @ W1 + b1) -> bf16
    {
        int N = 1024, K = 256, relu = 1, lda = 256;
        const __nv_bfloat16* Aarg = x1bf;
        const __nv_bfloat16* Warg = wbf + WOFF_1;
        float* C32 = nullptr;
        __nv_bfloat16* C16 = hbf;
        void* args[] = {(void*)&Aarg, (void*)&Warg, (void*)&b1,
                        (void*)&C32, (void*)&C16, (void*)&M, (void*)&N,
                        (void*)&K, (void*)&relu, (void*)&lda};
        launch_pdl((const void*)gemm_std_kernel,
                   dim3(16, MT), dim3(128), GEMM_SMEM_BYTES, args);
    }

    // 6) tmp = h @ W2 + b2
    {
        int N = 256, K = 1024, relu = 0, lda = 1024;
        const __nv_bfloat16* Aarg = hbf;
        const __nv_bfloat16* Warg = wbf + WOFF_2;
        float* C32 = tmp;
        __nv_bfloat16* C16 = nullptr;
        void* args[] = {(void*)&Aarg, (void*)&Warg, (void*)&b2,
                        (void*)&C32, (void*)&C16, (void*)&M, (void*)&N,
                        (void*)&K, (void*)&relu, (void*)&lda};
        launch_pdl((const void*)gemm_std_kernel,
                   dim3(4, MT), dim3(128), GEMM_SMEM_BYTES, args);
    }

    // 7) out = LN(x1 + tmp)
    {
        __nv_bfloat16* nobf = nullptr;
        void* args[] = {(void*)&x1, (void*)&tmp, (void*)&g2, (void*)&be2,
                        (void*)&out, (void*)&nobf};
        launch_pdl((const void*)add_ln_kernel, dim3(M), dim3(256), 0, args);
    }
}